// round 12
// baseline (speedup 1.0000x reference)
#include <cuda_runtime.h>
#include <cuda_fp16.h>
#include <cstdint>

// ---------------------------------------------------------------------------
// LSTM_41764261986630 : 2-layer LSTM, T=512, B=64, IN=H=512
// mma.sync (HMMA) single-term fp16, persistent, weight-stationary.
// R11: global grid barrier -> per-layer done counters + 4-deep h buffers.
//   layer0 chunks 0-3 = x (no wait); dependent-half poll hidden at chunk 3.
// ---------------------------------------------------------------------------

#define TSTEPS 512
#define BATCH  64
#define HID    512
#define BH     (BATCH*HID)
#define NCTA   128
#define NTHR   128

// SMEM byte offsets
#define SO_W    0          // 65536 B : [tile 0..127][256 fp16]
#define SO_A    65536      // 2 stages x 16384 B
#define SO_BIAS 98304      // 32 floats
#define SMEM_TOTAL 98432

// ---- persistent device scratch (no cudaMalloc allowed) ----
__device__ __align__(16) __half g_w[(size_t)NCTA*128*256];        // 8MB
__device__ __align__(16) __half g_x[(size_t)TSTEPS*32768];        // 32MB
__device__ __align__(16) __half g_h0[4*32768];                    // 4-deep
__device__ __align__(16) __half g_h1[4*32768];
__device__ unsigned g_bar;
__device__ volatile unsigned g_done0, g_done1;   // per-layer wave counters

// ---------------- helpers ----------------
__device__ __forceinline__ void cp_async16(void* sdst, const void* gsrc) {
    unsigned sa;
    asm("{ .reg .u64 t; cvta.to.shared.u64 t, %1; cvt.u32.u64 %0, t; }"
        : "=r"(sa) : "l"(sdst));
    asm volatile("cp.async.cg.shared.global [%0], [%1], 16;\n" :: "r"(sa), "l"(gsrc));
}
#define CP_COMMIT() asm volatile("cp.async.commit_group;\n")
#define CP_WAIT(n)  asm volatile("cp.async.wait_group %0;\n" :: "n"(n))

__device__ __forceinline__ void mma16816(float* d,
        uint32_t a0, uint32_t a1, uint32_t a2, uint32_t a3,
        uint32_t b0, uint32_t b1) {
    asm volatile(
      "mma.sync.aligned.m16n8k16.row.col.f32.f16.f16.f32 "
      "{%0,%1,%2,%3}, {%4,%5,%6,%7}, {%8,%9}, {%0,%1,%2,%3};"
      : "+f"(d[0]), "+f"(d[1]), "+f"(d[2]), "+f"(d[3])
      : "r"(a0), "r"(a1), "r"(a2), "r"(a3), "r"(b0), "r"(b1));
}

// fragment-order position of k-local element within a 16-wide act row
__device__ __host__ __forceinline__ int p_of_kl(int kl) {
    return ((kl & 7) >> 1) * 4 + ((kl >> 3) << 1) + (kl & 1);
}

// final barrier only (monotonic counter: safe across graph replays)
__device__ __forceinline__ void grid_sync() {
    __threadfence();
    __syncthreads();
    if (threadIdx.x == 0) {
        unsigned arrive = atomicAdd(&g_bar, 1u);
        unsigned target = (arrive / NCTA + 1u) * NCTA;
        while (*(volatile unsigned*)&g_bar < target) { }
        __threadfence();
    }
    __syncthreads();
}

// ---------------- prep kernels ----------------
// W fragment image per CTA: [tile ti = s*2+mb][lane L][8 fp16]
__global__ void prep_w(const float* __restrict__ Wx, const float* __restrict__ Wh) {
    const int blk = blockIdx.x;               // cta*8 + ch
    const int ch = blk & 7, cta = blk >> 3;
    const int layer = cta >> 6, hb = cta & 63;
    const float* wx = Wx + (size_t)layer * 2048 * 512;
    const float* wh = Wh + (size_t)layer * 2048 * 512;
    const size_t base = (size_t)cta * 128 * 256;
    for (int e = threadIdx.x; e < 16 * 256; e += blockDim.x) {
        int ti  = ch * 16 + (e >> 8);
        int q16 = e & 255;
        int L = q16 >> 3, eb = q16 & 7;
        int qreg = eb >> 1, half = eb & 1;
        int s = ti >> 1, mb = ti & 1;
        int m  = (L >> 2) + ((qreg & 1) << 3) + (mb << 4);   // row 0..31
        int kl = ((L & 3) << 1) + ((qreg >> 1) << 3) + half;
        int k  = (s << 4) + kl;
        int R  = (m >> 3) * 512 + hb * 8 + (m & 7);
        float v = (k < 512) ? wx[(size_t)R * 512 + k]
                            : wh[(size_t)R * 512 + (k - 512)];
        g_w[base + (size_t)ti * 256 + q16] = __float2half_rn(v);
    }
}

// x fragment image: [t][s 0..31][n 0..63][16], k-local position p = p_of_kl(kl)
__global__ void prep_x(const float* __restrict__ x) {
    const int t = blockIdx.x;
    const float* src = x + (size_t)t * BH;
    const size_t dst = (size_t)t * 32768;
    for (int e = threadIdx.x; e < 32768; e += blockDim.x) {
        int s = e >> 10, n = (e >> 4) & 63, p = e & 15;
        int q = p >> 2, r = p & 3;
        int kl = (q << 1) + (r & 1) + ((r >> 1) << 3);
        g_x[dst + e] = __float2half_rn(src[n * 512 + ((s << 4) + kl)]);
    }
}

// ---------------- main persistent kernel ----------------
__global__ void __launch_bounds__(NTHR, 1)
lstm_mma(const float* __restrict__ bh, float* __restrict__ out)
{
    extern __shared__ __align__(16) char smem[];
    const int tid = threadIdx.x;
    const int L = tid & 31, warp = tid >> 5;
    const int cta = blockIdx.x, layer = cta >> 6, hb = cta & 63;

    // ---- resident weight load (once) ----
    {
        const char* wsrc = (const char*)(g_w + (size_t)cta * 32768);
        for (int i = tid; i < 4096; i += NTHR)
            cp_async16(smem + SO_W + i * 16, wsrc + i * 16);
        CP_COMMIT();
    }
    float* bias_s = (float*)(smem + SO_BIAS);
    if (tid < 32)
        bias_s[tid] = bh[layer * 2048 + (tid >> 3) * 512 + hb * 8 + (tid & 7)];
    CP_WAIT(0);
    __syncthreads();

    // epilogue constants
    const int j  = L >> 2;                 // hidden within CTA (0..7)
    const int hh = hb * 8 + j;             // global hidden index
    const int sH = hh >> 4;
    const int pH = p_of_kl(hh & 15);
    const float bi = bias_s[j],      bf = bias_s[8 + j];
    const float bg = bias_s[16 + j], bo = bias_s[24 + j];

    float c_st[4] = {0.f, 0.f, 0.f, 0.f};
    float h_st[4] = {0.f, 0.f, 0.f, 0.f};

    const int n0 = (warp << 4) + (L >> 2);   // act row for nb=0
    const char* wbase = smem + SO_W;

    for (int w = 0; w <= TSTEPS; ++w) {
        const bool active = (layer == 0) ? (w < TSTEPS) : (w >= 1);
        if (active) {
            const int t = (layer == 0) ? w : (w - 1);
            const int nch = (t == 0) ? 4 : 8;

            const __half *Asrc, *Bsrc;
            if (layer == 0) {
                Asrc = g_x + (size_t)t * 32768;
                Bsrc = g_h0 + (size_t)((t - 1) & 3) * 32768;
            } else {
                Asrc = g_h0 + (size_t)(t & 3) * 32768;
                Bsrc = g_h1 + (size_t)((t - 1) & 3) * 32768;
            }

            // layer1: chunks 0-3 read h0[t] (layer0, wave w-1) — poll before
            // first prefetch.  With layer0 lookahead this is pre-satisfied.
            if (layer == 1) {
                if (tid == 0) {
                    const unsigned tgt = 64u * (unsigned)w;
                    while (g_done0 < tgt) { }
                    __threadfence();
                }
                __syncthreads();
            }

            float d[2][2][4];
            #pragma unroll
            for (int mb = 0; mb < 2; ++mb)
                #pragma unroll
                for (int nb = 0; nb < 2; ++nb)
                    #pragma unroll
                    for (int q = 0; q < 4; ++q) d[mb][nb][q] = 0.f;

            auto prefetch = [&](int c) {
                const int st = c & 1;
                const __half* s = (c < 4) ? Asrc + c * 8192 : Bsrc + (c - 4) * 8192;
                char* dst = smem + SO_A + st * 16384;
                #pragma unroll
                for (int i = 0; i < 8; ++i) {
                    int e = i * NTHR + tid;
                    cp_async16(dst + e * 16, (const char*)s + e * 16);
                }
                CP_COMMIT();
            };

            prefetch(0);
            for (int c = 0; c < nch; ++c) {
                // dependent half: poll own-layer previous wave before
                // prefetch(4); hidden under chunks 0-3 compute.
                if (c == 3 && nch == 8) {
                    if (tid == 0) {
                        if (layer == 0) {
                            const unsigned tgt0 = 64u * (unsigned)w;
                            while (g_done0 < tgt0) { }
                            if (w >= 3) {   // h0[w&3] reuse: layer1 past wave w-3
                                const unsigned tgt1 = 64u * (unsigned)(w - 3);
                                while (g_done1 < tgt1) { }
                            }
                        } else {
                            const unsigned tgt1 = 64u * (unsigned)(w - 1);
                            while (g_done1 < tgt1) { }
                        }
                        __threadfence();
                    }
                    __syncthreads();
                }
                if (c + 1 < nch) { prefetch(c + 1); CP_WAIT(1); }
                else             { CP_WAIT(0); }
                __syncthreads();

                const char* abase = smem + SO_A + (c & 1) * 16384;

                // fragment double buffer (one sl ahead)
                uint4 WH0[2], WH1[2];
                uint2 AH0[2], AH1[2];

                auto ldfrag = [&](int sl, int bufi) {
                    const int s2 = ((c << 3) + sl) << 1;
                    WH0[bufi] = *(const uint4*)(wbase + (size_t)(s2    ) * 512 + L * 16);
                    WH1[bufi] = *(const uint4*)(wbase + (size_t)(s2 + 1) * 512 + L * 16);
                    const int ro0 = ((sl << 6) + n0) * 32 + (L & 3) * 8;
                    AH0[bufi] = *(const uint2*)(abase + ro0);
                    AH1[bufi] = *(const uint2*)(abase + ro0 + 8 * 32);
                };

                ldfrag(0, 0);
                #pragma unroll
                for (int sl = 0; sl < 8; ++sl) {
                    const int cur = sl & 1;
                    if (sl < 7) ldfrag(sl + 1, cur ^ 1);

                    const uint4 wh0 = WH0[cur], wh1 = WH1[cur];
                    const uint2 ah0 = AH0[cur], ah1 = AH1[cur];

                    mma16816(d[0][0], wh0.x, wh0.y, wh0.z, wh0.w, ah0.x, ah0.y);
                    mma16816(d[0][1], wh0.x, wh0.y, wh0.z, wh0.w, ah1.x, ah1.y);
                    mma16816(d[1][0], wh1.x, wh1.y, wh1.z, wh1.w, ah0.x, ah0.y);
                    mma16816(d[1][1], wh1.x, wh1.y, wh1.z, wh1.w, ah1.x, ah1.y);
                }
                __syncthreads();
            }

            // ---- epilogue: gates; republish h (frag order, single fp16) ----
            __half* dh = (layer ? g_h1 : g_h0) + (size_t)(t & 3) * 32768;
            float* orow = out + (size_t)t * BH;
            #pragma unroll
            for (int nb = 0; nb < 2; ++nb) {
                #pragma unroll
                for (int cc = 0; cc < 2; ++cc) {
                    const int si = nb * 2 + cc;
                    const int b  = (warp << 4) + (nb << 3) + ((L & 3) << 1) + cc;
                    float pi = d[0][nb][cc]     + bi;
                    float pf = d[0][nb][2 + cc] + bf;
                    float pg = d[1][nb][cc]     + bg;
                    float po = d[1][nb][2 + cc] + bo;
                    float ig = __fdividef(1.f, 1.f + __expf(-pi));
                    float fg = __fdividef(1.f, 1.f + __expf(-pf));
                    float gt = 2.f * __fdividef(1.f, 1.f + __expf(-2.f * pg)) - 1.f;
                    float og = __fdividef(1.f, 1.f + __expf(-po));
                    float cn = fg * c_st[si] + ig * gt;
                    c_st[si] = cn;
                    float th = 2.f * __fdividef(1.f, 1.f + __expf(-2.f * cn)) - 1.f;
                    float hn = og * th;
                    h_st[si] = hn;
                    dh[sH * 1024 + b * 16 + pH] = __float2half_rn(hn);
                    if (layer == 1) orow[b * 512 + hh] = hn;
                }
            }

            // publish: writes visible, then bump own layer's counter
            __threadfence();
            __syncthreads();
            if (tid == 0) {
                if (layer == 0) atomicAdd((unsigned*)&g_done0, 1u);
                else            atomicAdd((unsigned*)&g_done1, 1u);
            }
        }
    }

    // ---- final h, c tails: out layout = [out | h(L,B,H) | c(L,B,H)] ----
    const size_t base = (size_t)TSTEPS * BH;
    #pragma unroll
    for (int nb = 0; nb < 2; ++nb)
        #pragma unroll
        for (int cc = 0; cc < 2; ++cc) {
            const int si = nb * 2 + cc;
            const int b  = (warp << 4) + (nb << 3) + ((L & 3) << 1) + cc;
            out[base + (size_t)layer * BH + (size_t)b * 512 + hh] = h_st[si];
            out[base + 2 * (size_t)BH + (size_t)layer * BH + (size_t)b * 512 + hh] = c_st[si];
        }

    // replay safety: all CTAs done -> reset wave counters to zero
    grid_sync();
    if (cta == 0 && tid == 0) { g_done0 = 0; g_done1 = 0; }
}

extern "C" void kernel_launch(void* const* d_in, const int* in_sizes, int n_in,
                              void* d_out, int out_size) {
    (void)in_sizes; (void)n_in; (void)out_size;
    const float* x  = (const float*)d_in[0];
    const float* Wx = (const float*)d_in[1];
    const float* Wh = (const float*)d_in[2];
    const float* bh = (const float*)d_in[3];
    float* out = (float*)d_out;

    prep_w<<<NCTA * 8, 128>>>(Wx, Wh);
    prep_x<<<TSTEPS, 256>>>(x);

    cudaFuncSetAttribute(lstm_mma, cudaFuncAttributeMaxDynamicSharedMemorySize,
                         SMEM_TOTAL);
    lstm_mma<<<NCTA, NTHR, SMEM_TOTAL>>>(bh, out);
}

// round 13
// speedup vs baseline: 1.1327x; 1.1327x over previous
#include <cuda_runtime.h>
#include <cuda_fp16.h>
#include <cstdint>

// ---------------------------------------------------------------------------
// LSTM_41764261986630 : 2-layer LSTM, T=512, B=64, IN=H=512
// mma.sync (HMMA) single-term fp16, persistent, weight-stationary.
// R12: K-split warp specialization — 256 thr/CTA, warps 0-3 compute the
// input half (chunks 0-3), warps 4-7 the recurrent half; partial-D reduced
// through SMEM at epilogue.  Same crossbar traffic as R10, 2 warps/SMSP
// latency hiding, half the chunk syncs.  Global barrier kept (R11 failed).
// ---------------------------------------------------------------------------

#define TSTEPS 512
#define BATCH  64
#define HID    512
#define BH     (BATCH*HID)
#define NCTA   128
#define NTHR   256

// SMEM byte offsets
#define SO_W    0          // 65536 B : [tile 0..127][256 fp16]
#define SO_A    65536      // 2 stages x 32768 B (x-plane 16K | h-plane 16K)
#define SO_RED  131072     // 4*32*17*4 = 8704 B partial-D staging
#define SO_BIAS 139776     // 32 floats
#define SMEM_TOTAL 139904

// ---- persistent device scratch (no cudaMalloc allowed) ----
__device__ __align__(16) __half g_w[(size_t)NCTA*128*256];        // 8MB
__device__ __align__(16) __half g_x[(size_t)TSTEPS*32768];        // 32MB
__device__ __align__(16) __half g_h0[2*32768];
__device__ __align__(16) __half g_h1[2*32768];
__device__ unsigned g_bar;

// ---------------- helpers ----------------
__device__ __forceinline__ void cp_async16(void* sdst, const void* gsrc) {
    unsigned sa;
    asm("{ .reg .u64 t; cvta.to.shared.u64 t, %1; cvt.u32.u64 %0, t; }"
        : "=r"(sa) : "l"(sdst));
    asm volatile("cp.async.cg.shared.global [%0], [%1], 16;\n" :: "r"(sa), "l"(gsrc));
}
#define CP_COMMIT() asm volatile("cp.async.commit_group;\n")
#define CP_WAIT(n)  asm volatile("cp.async.wait_group %0;\n" :: "n"(n))

__device__ __forceinline__ void mma16816(float* d,
        uint32_t a0, uint32_t a1, uint32_t a2, uint32_t a3,
        uint32_t b0, uint32_t b1) {
    asm volatile(
      "mma.sync.aligned.m16n8k16.row.col.f32.f16.f16.f32 "
      "{%0,%1,%2,%3}, {%4,%5,%6,%7}, {%8,%9}, {%0,%1,%2,%3};"
      : "+f"(d[0]), "+f"(d[1]), "+f"(d[2]), "+f"(d[3])
      : "r"(a0), "r"(a1), "r"(a2), "r"(a3), "r"(b0), "r"(b1));
}

// fragment-order position of k-local element within a 16-wide act row
__device__ __host__ __forceinline__ int p_of_kl(int kl) {
    return ((kl & 7) >> 1) * 4 + ((kl >> 3) << 1) + (kl & 1);
}

// grid barrier (monotonic counter: safe across graph replays)
__device__ __forceinline__ void grid_sync() {
    __threadfence();
    __syncthreads();
    if (threadIdx.x == 0) {
        unsigned arrive = atomicAdd(&g_bar, 1u);
        unsigned target = (arrive / NCTA + 1u) * NCTA;
        while (*(volatile unsigned*)&g_bar < target) { }
        __threadfence();
    }
    __syncthreads();
}

// ---------------- prep kernels ----------------
// W fragment image per CTA: [tile ti = s*2+mb][lane L][8 fp16]
__global__ void prep_w(const float* __restrict__ Wx, const float* __restrict__ Wh) {
    const int blk = blockIdx.x;               // cta*8 + ch
    const int ch = blk & 7, cta = blk >> 3;
    const int layer = cta >> 6, hb = cta & 63;
    const float* wx = Wx + (size_t)layer * 2048 * 512;
    const float* wh = Wh + (size_t)layer * 2048 * 512;
    const size_t base = (size_t)cta * 128 * 256;
    for (int e = threadIdx.x; e < 16 * 256; e += blockDim.x) {
        int ti  = ch * 16 + (e >> 8);
        int q16 = e & 255;
        int L = q16 >> 3, eb = q16 & 7;
        int qreg = eb >> 1, half = eb & 1;
        int s = ti >> 1, mb = ti & 1;
        int m  = (L >> 2) + ((qreg & 1) << 3) + (mb << 4);   // row 0..31
        int kl = ((L & 3) << 1) + ((qreg >> 1) << 3) + half;
        int k  = (s << 4) + kl;
        int R  = (m >> 3) * 512 + hb * 8 + (m & 7);
        float v = (k < 512) ? wx[(size_t)R * 512 + k]
                            : wh[(size_t)R * 512 + (k - 512)];
        g_w[base + (size_t)ti * 256 + q16] = __float2half_rn(v);
    }
}

// x fragment image: [t][s 0..31][n 0..63][16], k-local position p = p_of_kl(kl)
__global__ void prep_x(const float* __restrict__ x) {
    const int t = blockIdx.x;
    const float* src = x + (size_t)t * BH;
    const size_t dst = (size_t)t * 32768;
    for (int e = threadIdx.x; e < 32768; e += blockDim.x) {
        int s = e >> 10, n = (e >> 4) & 63, p = e & 15;
        int q = p >> 2, r = p & 3;
        int kl = (q << 1) + (r & 1) + ((r >> 1) << 3);
        g_x[dst + e] = __float2half_rn(src[n * 512 + ((s << 4) + kl)]);
    }
}

// ---------------- main persistent kernel ----------------
__global__ void __launch_bounds__(NTHR, 1)
lstm_mma(const float* __restrict__ bh, float* __restrict__ out)
{
    extern __shared__ __align__(16) char smem[];
    const int tid = threadIdx.x;
    const int L = tid & 31, warp = tid >> 5;
    const int p  = warp & 3;            // batch group 0..3
    const int kh = warp >> 2;           // k-half: 0 = input, 1 = recurrent
    const int cta = blockIdx.x, layer = cta >> 6, hb = cta & 63;

    // ---- resident weight load (once) ----
    {
        const char* wsrc = (const char*)(g_w + (size_t)cta * 32768);
        for (int i = tid; i < 4096; i += NTHR)
            cp_async16(smem + SO_W + i * 16, wsrc + i * 16);
        CP_COMMIT();
    }
    float* bias_s = (float*)(smem + SO_BIAS);
    if (tid < 32)
        bias_s[tid] = bh[layer * 2048 + (tid >> 3) * 512 + hb * 8 + (tid & 7)];
    CP_WAIT(0);
    __syncthreads();

    // epilogue constants
    const int j  = L >> 2;                 // hidden within CTA (0..7)
    const int hh = hb * 8 + j;             // global hidden index
    const int sH = hh >> 4;
    const int pH = p_of_kl(hh & 15);
    const float bi = bias_s[j],      bf = bias_s[8 + j];
    const float bg = bias_s[16 + j], bo = bias_s[24 + j];

    float c_st[4] = {0.f, 0.f, 0.f, 0.f};
    float h_st[4] = {0.f, 0.f, 0.f, 0.f};

    const int n0 = (p << 4) + (L >> 2);    // act row for nb=0
    const char* wbase = smem + SO_W;
    float* red = (float*)(smem + SO_RED);  // [p][L][17] floats

    for (int w = 0; w <= TSTEPS; ++w) {
        const bool active = (layer == 0) ? (w < TSTEPS) : (w >= 1);
        if (active) {
            const int t = (layer == 0) ? w : (w - 1);

            const __half *Asrc, *Bsrc;
            if (layer == 0) {
                Asrc = g_x + (size_t)t * 32768;
                Bsrc = g_h0 + (size_t)((t - 1) & 1) * 32768;
            } else {
                Asrc = g_h0 + (size_t)(t & 1) * 32768;
                Bsrc = g_h1 + (size_t)((t - 1) & 1) * 32768;
            }
            // this warp's compute enable (recurrent half is zero at t==0)
            const bool do_mma = (kh == 0) || (t != 0);

            float d[2][2][4];
            #pragma unroll
            for (int mb = 0; mb < 2; ++mb)
                #pragma unroll
                for (int nb = 0; nb < 2; ++nb)
                    #pragma unroll
                    for (int q = 0; q < 4; ++q) d[mb][nb][q] = 0.f;

            // stage both planes of chunk c: [x-plane 16K | h-plane 16K]
            auto prefetch = [&](int c) {
                const int st = c & 1;
                char* dst = smem + SO_A + st * 32768;
                const char* sa = (const char*)(Asrc + (size_t)c * 8192);
                const char* sb = (const char*)(Bsrc + (size_t)c * 8192);
                #pragma unroll
                for (int i = 0; i < 8; ++i) {
                    int e = i * NTHR + tid;            // 0..2047
                    const char* src = (e < 1024) ? sa + e * 16
                                                 : sb + (e - 1024) * 16;
                    cp_async16(dst + e * 16, src);
                }
                CP_COMMIT();
            };

            prefetch(0);
            for (int c = 0; c < 4; ++c) {
                if (c + 1 < 4) { prefetch(c + 1); CP_WAIT(1); }
                else           { CP_WAIT(0); }
                __syncthreads();

                if (do_mma) {
                    const char* abase = smem + SO_A + (c & 1) * 32768 + kh * 16384;
                    const int ck = (kh << 2) + c;      // global chunk 0..7

                    uint4 WH0[2], WH1[2];
                    uint2 AH0[2], AH1[2];
                    auto ldfrag = [&](int sl, int bufi) {
                        const int s2 = ((ck << 3) + sl) << 1;
                        WH0[bufi] = *(const uint4*)(wbase + (size_t)(s2    ) * 512 + L * 16);
                        WH1[bufi] = *(const uint4*)(wbase + (size_t)(s2 + 1) * 512 + L * 16);
                        const int ro0 = ((sl << 6) + n0) * 32 + (L & 3) * 8;
                        AH0[bufi] = *(const uint2*)(abase + ro0);
                        AH1[bufi] = *(const uint2*)(abase + ro0 + 8 * 32);
                    };

                    ldfrag(0, 0);
                    #pragma unroll
                    for (int sl = 0; sl < 8; ++sl) {
                        const int cur = sl & 1;
                        if (sl < 7) ldfrag(sl + 1, cur ^ 1);

                        const uint4 wh0 = WH0[cur], wh1 = WH1[cur];
                        const uint2 ah0 = AH0[cur], ah1 = AH1[cur];

                        mma16816(d[0][0], wh0.x, wh0.y, wh0.z, wh0.w, ah0.x, ah0.y);
                        mma16816(d[0][1], wh0.x, wh0.y, wh0.z, wh0.w, ah1.x, ah1.y);
                        mma16816(d[1][0], wh1.x, wh1.y, wh1.z, wh1.w, ah0.x, ah0.y);
                        mma16816(d[1][1], wh1.x, wh1.y, wh1.z, wh1.w, ah1.x, ah1.y);
                    }
                }
                __syncthreads();
            }

            // ---- epilogue: kh=1 stages partial D; kh=0 reduces + gates ----
            {
                float* r = red + ((p << 5) + L) * 17;
                if (kh == 1) {
                    #pragma unroll
                    for (int mb = 0; mb < 2; ++mb)
                        #pragma unroll
                        for (int nb = 0; nb < 2; ++nb)
                            #pragma unroll
                            for (int q = 0; q < 4; ++q)
                                r[(mb * 2 + nb) * 4 + q] = d[mb][nb][q];
                }
                __syncthreads();
                if (kh == 0) {
                    __half* dh = (layer ? g_h1 : g_h0) + (size_t)(t & 1) * 32768;
                    float* orow = out + (size_t)t * BH;
                    #pragma unroll
                    for (int nb = 0; nb < 2; ++nb) {
                        #pragma unroll
                        for (int cc = 0; cc < 2; ++cc) {
                            const int si = nb * 2 + cc;
                            const int b  = (p << 4) + (nb << 3) + ((L & 3) << 1) + cc;
                            float pi = d[0][nb][cc]     + r[nb * 4 + cc]           + bi;
                            float pf = d[0][nb][2 + cc] + r[nb * 4 + 2 + cc]       + bf;
                            float pg = d[1][nb][cc]     + r[(2 + nb) * 4 + cc]     + bg;
                            float po = d[1][nb][2 + cc] + r[(2 + nb) * 4 + 2 + cc] + bo;
                            float ig = __fdividef(1.f, 1.f + __expf(-pi));
                            float fg = __fdividef(1.f, 1.f + __expf(-pf));
                            float gt = 2.f * __fdividef(1.f, 1.f + __expf(-2.f * pg)) - 1.f;
                            float og = __fdividef(1.f, 1.f + __expf(-po));
                            float cn = fg * c_st[si] + ig * gt;
                            c_st[si] = cn;
                            float th = 2.f * __fdividef(1.f, 1.f + __expf(-2.f * cn)) - 1.f;
                            float hn = og * th;
                            h_st[si] = hn;
                            dh[sH * 1024 + b * 16 + pH] = __float2half_rn(hn);
                            if (layer == 1) orow[b * 512 + hh] = hn;
                        }
                    }
                }
            }
        }
        grid_sync();
    }

    // ---- final h, c tails: out layout = [out | h(L,B,H) | c(L,B,H)] ----
    if (kh == 0) {
        const size_t base = (size_t)TSTEPS * BH;
        #pragma unroll
        for (int nb = 0; nb < 2; ++nb)
            #pragma unroll
            for (int cc = 0; cc < 2; ++cc) {
                const int si = nb * 2 + cc;
                const int b  = (p << 4) + (nb << 3) + ((L & 3) << 1) + cc;
                out[base + (size_t)layer * BH + (size_t)b * 512 + hh] = h_st[si];
                out[base + 2 * (size_t)BH + (size_t)layer * BH + (size_t)b * 512 + hh] = c_st[si];
            }
    }
}

extern "C" void kernel_launch(void* const* d_in, const int* in_sizes, int n_in,
                              void* d_out, int out_size) {
    (void)in_sizes; (void)n_in; (void)out_size;
    const float* x  = (const float*)d_in[0];
    const float* Wx = (const float*)d_in[1];
    const float* Wh = (const float*)d_in[2];
    const float* bh = (const float*)d_in[3];
    float* out = (float*)d_out;

    prep_w<<<NCTA * 8, 128>>>(Wx, Wh);
    prep_x<<<TSTEPS, 256>>>(x);

    cudaFuncSetAttribute(lstm_mma, cudaFuncAttributeMaxDynamicSharedMemorySize,
                         SMEM_TOTAL);
    lstm_mma<<<NCTA, NTHR, SMEM_TOTAL>>>(bh, out);
}

// round 14
// speedup vs baseline: 1.3621x; 1.2025x over previous
#include <cuda_runtime.h>
#include <cuda_fp16.h>
#include <cstdint>

// ---------------------------------------------------------------------------
// LSTM_41764261986630 : 2-layer LSTM, T=512, B=64, IN=H=512
// mma.sync (HMMA) single-term fp16, persistent, weight-stationary.
// R13: activations loaded DIRECTLY from L2 via LDG.64 register pipeline
// (no SMEM staging, no chunk syncs).  SMEM port now carries only W reads.
// Warp layout from R12: 8 warps = k-half (kh) x batch-quad (p); partial-D
// reduced through SMEM at epilogue.  One grid barrier per wave.
// ---------------------------------------------------------------------------

#define TSTEPS 512
#define BATCH  64
#define HID    512
#define BH     (BATCH*HID)
#define NCTA   128
#define NTHR   256

// SMEM byte offsets
#define SO_W    0          // 65536 B : [tile 0..127][256 fp16]
#define SO_RED  65536      // 4*32*17*4 = 8704 B partial-D staging
#define SO_BIAS 74240      // 32 floats
#define SMEM_TOTAL 74368

// ---- persistent device scratch (no cudaMalloc allowed) ----
__device__ __align__(16) __half g_w[(size_t)NCTA*128*256];        // 8MB
__device__ __align__(16) __half g_x[(size_t)TSTEPS*32768];        // 32MB
__device__ __align__(16) __half g_h0[2*32768];
__device__ __align__(16) __half g_h1[2*32768];
__device__ unsigned g_bar;

// ---------------- helpers ----------------
__device__ __forceinline__ void cp_async16(void* sdst, const void* gsrc) {
    unsigned sa;
    asm("{ .reg .u64 t; cvta.to.shared.u64 t, %1; cvt.u32.u64 %0, t; }"
        : "=r"(sa) : "l"(sdst));
    asm volatile("cp.async.cg.shared.global [%0], [%1], 16;\n" :: "r"(sa), "l"(gsrc));
}
#define CP_COMMIT() asm volatile("cp.async.commit_group;\n")
#define CP_WAIT(n)  asm volatile("cp.async.wait_group %0;\n" :: "n"(n))

__device__ __forceinline__ void mma16816(float* d,
        uint32_t a0, uint32_t a1, uint32_t a2, uint32_t a3,
        uint32_t b0, uint32_t b1) {
    asm volatile(
      "mma.sync.aligned.m16n8k16.row.col.f32.f16.f16.f32 "
      "{%0,%1,%2,%3}, {%4,%5,%6,%7}, {%8,%9}, {%0,%1,%2,%3};"
      : "+f"(d[0]), "+f"(d[1]), "+f"(d[2]), "+f"(d[3])
      : "r"(a0), "r"(a1), "r"(a2), "r"(a3), "r"(b0), "r"(b1));
}

// fragment-order position of k-local element within a 16-wide act row
__device__ __host__ __forceinline__ int p_of_kl(int kl) {
    return ((kl & 7) >> 1) * 4 + ((kl >> 3) << 1) + (kl & 1);
}

// grid barrier (monotonic counter: safe across graph replays)
__device__ __forceinline__ void grid_sync() {
    __threadfence();
    __syncthreads();
    if (threadIdx.x == 0) {
        unsigned arrive = atomicAdd(&g_bar, 1u);
        unsigned target = (arrive / NCTA + 1u) * NCTA;
        while (*(volatile unsigned*)&g_bar < target) { }
        __threadfence();
    }
    __syncthreads();
}

// ---------------- prep kernels ----------------
// W fragment image per CTA: [tile ti = s*2+mb][lane L][8 fp16]
__global__ void prep_w(const float* __restrict__ Wx, const float* __restrict__ Wh) {
    const int blk = blockIdx.x;               // cta*8 + ch
    const int ch = blk & 7, cta = blk >> 3;
    const int layer = cta >> 6, hb = cta & 63;
    const float* wx = Wx + (size_t)layer * 2048 * 512;
    const float* wh = Wh + (size_t)layer * 2048 * 512;
    const size_t base = (size_t)cta * 128 * 256;
    for (int e = threadIdx.x; e < 16 * 256; e += blockDim.x) {
        int ti  = ch * 16 + (e >> 8);
        int q16 = e & 255;
        int L = q16 >> 3, eb = q16 & 7;
        int qreg = eb >> 1, half = eb & 1;
        int s = ti >> 1, mb = ti & 1;
        int m  = (L >> 2) + ((qreg & 1) << 3) + (mb << 4);   // row 0..31
        int kl = ((L & 3) << 1) + ((qreg >> 1) << 3) + half;
        int k  = (s << 4) + kl;
        int R  = (m >> 3) * 512 + hb * 8 + (m & 7);
        float v = (k < 512) ? wx[(size_t)R * 512 + k]
                            : wh[(size_t)R * 512 + (k - 512)];
        g_w[base + (size_t)ti * 256 + q16] = __float2half_rn(v);
    }
}

// x fragment image: [t][s 0..31][n 0..63][16], k-local position p = p_of_kl(kl)
__global__ void prep_x(const float* __restrict__ x) {
    const int t = blockIdx.x;
    const float* src = x + (size_t)t * BH;
    const size_t dst = (size_t)t * 32768;
    for (int e = threadIdx.x; e < 32768; e += blockDim.x) {
        int s = e >> 10, n = (e >> 4) & 63, p = e & 15;
        int q = p >> 2, r = p & 3;
        int kl = (q << 1) + (r & 1) + ((r >> 1) << 3);
        g_x[dst + e] = __float2half_rn(src[n * 512 + ((s << 4) + kl)]);
    }
}

// ---------------- main persistent kernel ----------------
__global__ void __launch_bounds__(NTHR, 1)
lstm_mma(const float* __restrict__ bh, float* __restrict__ out)
{
    extern __shared__ __align__(16) char smem[];
    const int tid = threadIdx.x;
    const int L = tid & 31, warp = tid >> 5;
    const int p  = warp & 3;            // batch group 0..3
    const int kh = warp >> 2;           // k-half: 0 = input, 1 = recurrent
    const int cta = blockIdx.x, layer = cta >> 6, hb = cta & 63;

    // ---- resident weight load (once) ----
    {
        const char* wsrc = (const char*)(g_w + (size_t)cta * 32768);
        for (int i = tid; i < 4096; i += NTHR)
            cp_async16(smem + SO_W + i * 16, wsrc + i * 16);
        CP_COMMIT();
    }
    float* bias_s = (float*)(smem + SO_BIAS);
    if (tid < 32)
        bias_s[tid] = bh[layer * 2048 + (tid >> 3) * 512 + hb * 8 + (tid & 7)];
    CP_WAIT(0);
    __syncthreads();

    // epilogue constants
    const int j  = L >> 2;                 // hidden within CTA (0..7)
    const int hh = hb * 8 + j;             // global hidden index
    const int sH = hh >> 4;
    const int pH = p_of_kl(hh & 15);
    const float bi = bias_s[j],      bf = bias_s[8 + j];
    const float bg = bias_s[16 + j], bo = bias_s[24 + j];

    float c_st[4] = {0.f, 0.f, 0.f, 0.f};
    float h_st[4] = {0.f, 0.f, 0.f, 0.f};

    const int n0 = (p << 4) + (L >> 2);    // act row for nb=0
    const char* wbase = smem + SO_W;
    float* red = (float*)(smem + SO_RED);  // [p][L][17] floats

    // per-lane byte offset inside a 32KB act plane: (s*64 + n)*32 + (L&3)*8
    const int aoff = n0 * 32 + (L & 3) * 8;

    for (int w = 0; w <= TSTEPS; ++w) {
        const bool active = (layer == 0) ? (w < TSTEPS) : (w >= 1);
        if (active) {
            const int t = (layer == 0) ? w : (w - 1);

            const __half *Asrc, *Bsrc;
            if (layer == 0) {
                Asrc = g_x + (size_t)t * 32768;
                Bsrc = g_h0 + (size_t)((t - 1) & 1) * 32768;
            } else {
                Asrc = g_h0 + (size_t)(t & 1) * 32768;
                Bsrc = g_h1 + (size_t)((t - 1) & 1) * 32768;
            }
            // this warp's compute enable (recurrent half is zero at t==0)
            const bool do_mma = (kh == 0) || (t != 0);

            float d[2][2][4];
            #pragma unroll
            for (int mb = 0; mb < 2; ++mb)
                #pragma unroll
                for (int nb = 0; nb < 2; ++nb)
                    #pragma unroll
                    for (int q = 0; q < 4; ++q) d[mb][nb][q] = 0.f;

            if (do_mma) {
                const char* ag = (const char*)(kh ? Bsrc : Asrc) + aoff;

                // A register pipeline, depth 4 (LDG.64 direct from L2)
                uint2 A0[4], A1[4];
                #pragma unroll
                for (int i = 0; i < 4; ++i) {
                    A0[i] = *(const uint2*)(ag + i * 2048);
                    A1[i] = *(const uint2*)(ag + i * 2048 + 256);
                }
                // W double buffer from SMEM
                uint4 WH0[2], WH1[2];
                {
                    const int s2 = (kh << 6);
                    WH0[0] = *(const uint4*)(wbase + (size_t)(s2    ) * 512 + L * 16);
                    WH1[0] = *(const uint4*)(wbase + (size_t)(s2 + 1) * 512 + L * 16);
                }

                #pragma unroll
                for (int s = 0; s < 32; ++s) {
                    const int cur = s & 1, slot = s & 3;
                    if (s < 31) {
                        const int s2 = ((kh << 5) + s + 1) << 1;
                        WH0[cur ^ 1] = *(const uint4*)(wbase + (size_t)(s2    ) * 512 + L * 16);
                        WH1[cur ^ 1] = *(const uint4*)(wbase + (size_t)(s2 + 1) * 512 + L * 16);
                    }
                    const uint2 ah0 = A0[slot], ah1 = A1[slot];
                    if (s + 4 < 32) {
                        A0[slot] = *(const uint2*)(ag + (s + 4) * 2048);
                        A1[slot] = *(const uint2*)(ag + (s + 4) * 2048 + 256);
                    }
                    const uint4 wh0 = WH0[cur], wh1 = WH1[cur];

                    mma16816(d[0][0], wh0.x, wh0.y, wh0.z, wh0.w, ah0.x, ah0.y);
                    mma16816(d[0][1], wh0.x, wh0.y, wh0.z, wh0.w, ah1.x, ah1.y);
                    mma16816(d[1][0], wh1.x, wh1.y, wh1.z, wh1.w, ah0.x, ah0.y);
                    mma16816(d[1][1], wh1.x, wh1.y, wh1.z, wh1.w, ah1.x, ah1.y);
                }
            }

            // ---- epilogue: kh=1 stages partial D; kh=0 reduces + gates ----
            {
                float* r = red + ((p << 5) + L) * 17;
                if (kh == 1) {
                    #pragma unroll
                    for (int mb = 0; mb < 2; ++mb)
                        #pragma unroll
                        for (int nb = 0; nb < 2; ++nb)
                            #pragma unroll
                            for (int q = 0; q < 4; ++q)
                                r[(mb * 2 + nb) * 4 + q] = d[mb][nb][q];
                }
                __syncthreads();
                if (kh == 0) {
                    __half* dh = (layer ? g_h1 : g_h0) + (size_t)(t & 1) * 32768;
                    float* orow = out + (size_t)t * BH;
                    #pragma unroll
                    for (int nb = 0; nb < 2; ++nb) {
                        #pragma unroll
                        for (int cc = 0; cc < 2; ++cc) {
                            const int si = nb * 2 + cc;
                            const int b  = (p << 4) + (nb << 3) + ((L & 3) << 1) + cc;
                            float pi = d[0][nb][cc]     + r[nb * 4 + cc]           + bi;
                            float pf = d[0][nb][2 + cc] + r[nb * 4 + 2 + cc]       + bf;
                            float pg = d[1][nb][cc]     + r[(2 + nb) * 4 + cc]     + bg;
                            float po = d[1][nb][2 + cc] + r[(2 + nb) * 4 + 2 + cc] + bo;
                            float ig = __fdividef(1.f, 1.f + __expf(-pi));
                            float fg = __fdividef(1.f, 1.f + __expf(-pf));
                            float gt = 2.f * __fdividef(1.f, 1.f + __expf(-2.f * pg)) - 1.f;
                            float og = __fdividef(1.f, 1.f + __expf(-po));
                            float cn = fg * c_st[si] + ig * gt;
                            c_st[si] = cn;
                            float th = 2.f * __fdividef(1.f, 1.f + __expf(-2.f * cn)) - 1.f;
                            float hn = og * th;
                            h_st[si] = hn;
                            dh[sH * 1024 + b * 16 + pH] = __float2half_rn(hn);
                            if (layer == 1) orow[b * 512 + hh] = hn;
                        }
                    }
                }
            }
        }
        grid_sync();
    }

    // ---- final h, c tails: out layout = [out | h(L,B,H) | c(L,B,H)] ----
    if (kh == 0) {
        const size_t base = (size_t)TSTEPS * BH;
        #pragma unroll
        for (int nb = 0; nb < 2; ++nb)
            #pragma unroll
            for (int cc = 0; cc < 2; ++cc) {
                const int si = nb * 2 + cc;
                const int b  = (p << 4) + (nb << 3) + ((L & 3) << 1) + cc;
                out[base + (size_t)layer * BH + (size_t)b * 512 + hh] = h_st[si];
                out[base + 2 * (size_t)BH + (size_t)layer * BH + (size_t)b * 512 + hh] = c_st[si];
            }
    }
}

extern "C" void kernel_launch(void* const* d_in, const int* in_sizes, int n_in,
                              void* d_out, int out_size) {
    (void)in_sizes; (void)n_in; (void)out_size;
    const float* x  = (const float*)d_in[0];
    const float* Wx = (const float*)d_in[1];
    const float* Wh = (const float*)d_in[2];
    const float* bh = (const float*)d_in[3];
    float* out = (float*)d_out;

    prep_w<<<NCTA * 8, 128>>>(Wx, Wh);
    prep_x<<<TSTEPS, 256>>>(x);

    cudaFuncSetAttribute(lstm_mma, cudaFuncAttributeMaxDynamicSharedMemorySize,
                         SMEM_TOTAL);
    lstm_mma<<<NCTA, NTHR, SMEM_TOTAL>>>(bh, out);
}